// round 15
// baseline (speedup 1.0000x reference)
#include <cuda_runtime.h>
#include <cuda_bf16.h>
#include <math.h>
#include <cstdint>

// Problem constants
#define BATCH 8
#define CCH   256
#define NPIX  1024
#define DHEAD 32
#define OC_ALL 320          // 32 q + 32 k + 256 v
#define KA    40            // augmented K padded to 40 (34 used)
#define ASTR2 44            // row stride for q'/k' (conflict-free tf32 frags)

// Scratch (device globals)
__device__ __nv_bfloat16 g_Vb[BATCH * CCH * NPIX];       // V projections, bf16
__device__ float g_qa[BATCH * NPIX * ASTR2];             // augmented scaled q rows (tf32)
__device__ float g_ka[BATCH * NPIX * ASTR2];             // augmented k rows (tf32)

// ===========================================================================
// helpers
// ===========================================================================
__device__ __forceinline__ float f2tf32(float f) {
    uint32_t u;
    asm("cvt.rna.tf32.f32 %0, %1;" : "=r"(u) : "f"(f));
    return __uint_as_float(u);
}
__device__ __forceinline__ float4 cvt4(float4 v) {
    v.x = f2tf32(v.x); v.y = f2tf32(v.y); v.z = f2tf32(v.z); v.w = f2tf32(v.w);
    return v;
}
__device__ __forceinline__ void mma_tf32(float* d, const uint32_t* a, const uint32_t* b) {
    asm volatile(
        "mma.sync.aligned.m16n8k8.row.col.f32.tf32.tf32.f32 "
        "{%0,%1,%2,%3}, {%4,%5,%6,%7}, {%8,%9}, {%0,%1,%2,%3};\n"
        : "+f"(d[0]), "+f"(d[1]), "+f"(d[2]), "+f"(d[3])
        : "r"(a[0]), "r"(a[1]), "r"(a[2]), "r"(a[3]), "r"(b[0]), "r"(b[1]));
}
__device__ __forceinline__ void mma_bf16(float* d, const uint32_t* a, const uint32_t* b) {
    asm volatile(
        "mma.sync.aligned.m16n8k16.row.col.f32.bf16.bf16.f32 "
        "{%0,%1,%2,%3}, {%4,%5,%6,%7}, {%8,%9}, {%0,%1,%2,%3};\n"
        : "+f"(d[0]), "+f"(d[1]), "+f"(d[2]), "+f"(d[3])
        : "r"(a[0]), "r"(a[1]), "r"(a[2]), "r"(a[3]), "r"(b[0]), "r"(b[1]));
}
__device__ __forceinline__ void ldmatrix_x4(uint32_t& r0, uint32_t& r1, uint32_t& r2,
                                            uint32_t& r3, uint32_t addr) {
    asm volatile("ldmatrix.sync.aligned.m8n8.x4.shared.b16 {%0,%1,%2,%3}, [%4];"
        : "=r"(r0), "=r"(r1), "=r"(r2), "=r"(r3) : "r"(addr));
}

// ---------------------------------------------------------------------------
// 1) Projection GEMM (tf32 mma), 512 threads, tile 128m x 256n, 96 CTAs:
//    rows 0..63 (q,k) -> smem -> augmented g_qa/g_ka (augment folded in)
//    rows 64..319 (v) -> g_Vb (bf16)
// ---------------------------------------------------------------------------
#define ASTR 36
#define BSTR_P 264
#define BN_P 256
#define QK_LD 264
#define PROJ_SMEM ((2 * 128 * ASTR + 2 * 32 * BSTR_P) * (int)sizeof(float))   // 104448

__global__ __launch_bounds__(512) void proj_gemm_mma(const float* __restrict__ x,
                                                     const float* __restrict__ Wq,
                                                     const float* __restrict__ bq,
                                                     const float* __restrict__ Wk,
                                                     const float* __restrict__ bk,
                                                     const float* __restrict__ Wv,
                                                     const float* __restrict__ bv,
                                                     const float* __restrict__ Wr) {
    int b  = blockIdx.z;
    int m0 = blockIdx.y * 128;
    int n0 = blockIdx.x * BN_P;
    const float* X = x + (size_t)b * CCH * NPIX;

    extern __shared__ float sm[];
    float* As = sm;
    float* Bs = sm + 2 * 128 * ASTR;

    int tid = threadIdx.x, warp = tid >> 5, lane = tid & 31;
    int wm = warp >> 3, wn = warp & 7;          // 2(m) x 8(n) warps; warp tile m64 x n32
    int g = lane >> 2, tg = lane & 3;

    float acc[4][4][4];
    #pragma unroll
    for (int i = 0; i < 4; i++)
        #pragma unroll
        for (int j = 0; j < 4; j++)
            #pragma unroll
            for (int r = 0; r < 4; r++) acc[i][j][r] = 0.f;

    // staging indices
    int arow[2], akq[2];                        // A: 128 x 32 = 1024 float4
    const float* wbase[2];
    #pragma unroll
    for (int u = 0; u < 2; u++) {
        int idx = tid + u * 512;
        arow[u] = idx >> 3;  akq[u] = (idx & 7) * 4;
        int r = m0 + arow[u];
        if (r < 32)       wbase[u] = Wq + (size_t)r * CCH;
        else if (r < 64)  wbase[u] = Wk + (size_t)(r - 32) * CCH;
        else if (r < 320) wbase[u] = Wv + (size_t)(r - 64) * CCH;
        else              wbase[u] = nullptr;
    }
    int brow[4], bnq[4];                        // B: 32 x 256 = 2048 float4
    #pragma unroll
    for (int u = 0; u < 4; u++) {
        int idx = tid + u * 512;
        brow[u] = idx >> 6;  bnq[u] = (idx & 63) * 4;
    }

    float4 pa[2], pb[4];
    #pragma unroll
    for (int u = 0; u < 2; u++)
        pa[u] = wbase[u] ? *(const float4*)&wbase[u][akq[u]] : make_float4(0.f, 0.f, 0.f, 0.f);
    #pragma unroll
    for (int u = 0; u < 4; u++)
        pb[u] = *(const float4*)&X[(size_t)brow[u] * NPIX + n0 + bnq[u]];
    #pragma unroll
    for (int u = 0; u < 2; u++)
        *(float4*)&As[arow[u] * ASTR + akq[u]] = cvt4(pa[u]);
    #pragma unroll
    for (int u = 0; u < 4; u++)
        *(float4*)&Bs[brow[u] * BSTR_P + bnq[u]] = cvt4(pb[u]);
    __syncthreads();

    #pragma unroll 1
    for (int t = 0; t < 8; t++) {
        if (t < 7) {
            int k0 = (t + 1) * 32;
            #pragma unroll
            for (int u = 0; u < 2; u++)
                pa[u] = wbase[u] ? *(const float4*)&wbase[u][k0 + akq[u]]
                                 : make_float4(0.f, 0.f, 0.f, 0.f);
            #pragma unroll
            for (int u = 0; u < 4; u++)
                pb[u] = *(const float4*)&X[(size_t)(k0 + brow[u]) * NPIX + n0 + bnq[u]];
        }
        const float* A = As + (t & 1) * 128 * ASTR;
        const float* B = Bs + (t & 1) * 32 * BSTR_P;
        #pragma unroll
        for (int kk = 0; kk < 32; kk += 8) {
            uint32_t af[4][4], bf[4][2];
            #pragma unroll
            for (int mt = 0; mt < 4; mt++) {
                int r = wm * 64 + mt * 16 + g;
                af[mt][0] = __float_as_uint(A[r * ASTR + kk + tg]);
                af[mt][1] = __float_as_uint(A[(r + 8) * ASTR + kk + tg]);
                af[mt][2] = __float_as_uint(A[r * ASTR + kk + tg + 4]);
                af[mt][3] = __float_as_uint(A[(r + 8) * ASTR + kk + tg + 4]);
            }
            #pragma unroll
            for (int nt = 0; nt < 4; nt++) {
                int nc = wn * 32 + nt * 8 + g;
                bf[nt][0] = __float_as_uint(B[(kk + tg) * BSTR_P + nc]);
                bf[nt][1] = __float_as_uint(B[(kk + tg + 4) * BSTR_P + nc]);
            }
            #pragma unroll
            for (int mt = 0; mt < 4; mt++)
                #pragma unroll
                for (int nt = 0; nt < 4; nt++)
                    mma_tf32(acc[mt][nt], af[mt], bf[nt]);
        }
        if (t < 7) {
            float* An = As + ((t + 1) & 1) * 128 * ASTR;
            float* Bn = Bs + ((t + 1) & 1) * 32 * BSTR_P;
            #pragma unroll
            for (int u = 0; u < 2; u++)
                *(float4*)&An[arow[u] * ASTR + akq[u]] = cvt4(pa[u]);
            #pragma unroll
            for (int u = 0; u < 4; u++)
                *(float4*)&Bn[brow[u] * BSTR_P + bnq[u]] = cvt4(pb[u]);
        }
        __syncthreads();
    }

    // epilogue: q,k rows (<64) -> smem QKs; v rows -> g_Vb bf16
    float* QKs = sm;   // reuse: 64 x 264 floats = 67584 B < 104448 B
    #pragma unroll
    for (int mt = 0; mt < 4; mt++) {
        int rbase = m0 + wm * 64 + mt * 16 + g;
        #pragma unroll
        for (int half = 0; half < 2; half++) {
            int r = rbase + half * 8;
            if (r >= OC_ALL) continue;
            float bias = (r < 32) ? bq[r] : (r < 64) ? bk[r - 32] : bv[r - 64];
            #pragma unroll
            for (int nt = 0; nt < 4; nt++) {
                int cl = wn * 32 + nt * 8 + 2 * tg;
                float v0 = acc[mt][nt][half * 2 + 0] + bias;
                float v1 = acc[mt][nt][half * 2 + 1] + bias;
                if (r < 64) {
                    QKs[r * QK_LD + cl]     = v0;
                    QKs[r * QK_LD + cl + 1] = v1;
                } else {
                    *(__nv_bfloat162*)&g_Vb[((size_t)b * CCH + (r - 64)) * NPIX + n0 + cl] =
                        __floats2bfloat162_rn(v0, v1);
                }
            }
        }
    }
    if (m0 != 0) return;
    __syncthreads();

    // augment (m-tile 0 only): 256 threads, one pixel each
    if (tid < BN_P) {
        int n = n0 + tid;
        float a0 = 0.f, a1 = 0.f;
        float q[DHEAD];
        #pragma unroll
        for (int d = 0; d < DHEAD; d++) {
            q[d] = QKs[d * QK_LD + tid];
            a0 += q[d] * Wr[2 * d];
            a1 += q[d] * Wr[2 * d + 1];
        }
        const float scale = rsqrtf((float)DHEAD);
        float* qrow = g_qa + (size_t)(b * NPIX + n) * ASTR2;
        #pragma unroll
        for (int d = 0; d < DHEAD; d++) qrow[d] = f2tf32(q[d] * scale);
        qrow[32] = f2tf32(a0 * scale);
        qrow[33] = f2tf32(a1 * scale);
        #pragma unroll
        for (int d = 34; d < KA; d++) qrow[d] = 0.f;

        float* krow = g_ka + (size_t)(b * NPIX + n) * ASTR2;
        #pragma unroll
        for (int d = 0; d < DHEAD; d++) krow[d] = f2tf32(QKs[(32 + d) * QK_LD + tid]);
        int hi = n >> 5, wi = n & 31;
        krow[32] = f2tf32(-(float)hi * (1.f / 31.f));
        krow[33] = f2tf32(-(float)wi * (1.f / 31.f));
        #pragma unroll
        for (int d = 34; d < KA; d++) krow[d] = 0.f;
    }
}

// ---------------------------------------------------------------------------
// 2) Fused attention (pipelined, AV fragments via ldmatrix.x4) — unchanged
// ---------------------------------------------------------------------------
#define IB 64
#define JT 128
#define PSTRH 136
#define VS_ELEMS (CCH * PSTRH)                  // bf16 elems per Vs buffer
// byte offsets in dynamic smem
#define QS_B 0
#define KS_B (QS_B + IB * ASTR2 * 4)            // 11264
#define PS_B (KS_B + JT * ASTR2 * 4)            // 33792
#define VS_B (PS_B + IB * PSTRH * 2)            // 51200
#define RS_B (VS_B + 2 * VS_ELEMS * 2)          // 190464
#define RI_B (RS_B + IB * 4)
#define FUSED_SMEM (RI_B + IB * 4)              // 190976

__global__ __launch_bounds__(512) void fused_attn(const float* __restrict__ x,
                                                  const float* __restrict__ gamma,
                                                  float* __restrict__ out) {
    int b  = blockIdx.y;
    int i0 = blockIdx.x * IB;
    const float* qab = g_qa + (size_t)b * NPIX * ASTR2;
    const float* kab = g_ka + (size_t)b * NPIX * ASTR2;
    const __nv_bfloat16* Vg = g_Vb + (size_t)b * CCH * NPIX;

    extern __shared__ char smc[];
    float* Qs = (float*)(smc + QS_B);
    float* Ks = (float*)(smc + KS_B);
    __nv_bfloat16* PsH = (__nv_bfloat16*)(smc + PS_B);
    __nv_bfloat16* VsH = (__nv_bfloat16*)(smc + VS_B);
    float* rs = (float*)(smc + RS_B);
    float* ri = (float*)(smc + RI_B);
    uint32_t smem_u = (uint32_t)__cvta_generic_to_shared(smc);

    int tid = threadIdx.x, warp = tid >> 5, lane = tid & 31;
    int wq = warp >> 3, wr = warp & 7;          // 2 (i) x 8 (j/ch) warp grid
    int g = lane >> 2, tg = lane & 3;

    // ldmatrix lane addresses (byte, shared space)
    uint32_t psA[2], vsB[2];
    {
        int sub = lane & 7;
        int ar = wq * 32 + ((lane >> 3) & 1) * 8 + sub;   // A: row
        int ac = (lane >> 4) * 8;                         // A: col (k)
        psA[0] = smem_u + PS_B + (uint32_t)(ar * PSTRH + ac) * 2;
        psA[1] = psA[0] + 16 * PSTRH * 2;
        int br = wr * 32 + (lane >> 4) * 8 + sub;         // B: row (channel)
        int bc = ((lane >> 3) & 1) * 8;                   // B: col (k)
        vsB[0] = smem_u + VS_B + (uint32_t)(br * PSTRH + bc) * 2;
        vsB[1] = vsB[0] + 16 * PSTRH * 2;
    }

    if (tid < IB) rs[tid] = 0.f;

    // prologue: stage Qs (64 x 40 fp32), Ks(0), prefetch V(0)
    for (int idx = tid; idx < 640; idx += 512) {
        int row = idx / 10, c4 = (idx % 10) * 4;
        *(float4*)&Qs[row * ASTR2 + c4] = *(const float4*)&qab[(size_t)(i0 + row) * ASTR2 + c4];
    }
    for (int idx = tid; idx < 1280; idx += 512) {
        int row = idx / 10, c4 = (idx % 10) * 4;
        *(float4*)&Ks[row * ASTR2 + c4] = *(const float4*)&kab[(size_t)row * ASTR2 + c4];
    }
    int vrow[8], vq8[8];
    uint4 pv[8];
    #pragma unroll
    for (int u = 0; u < 8; u++) {
        int idx = tid + u * 512;
        vrow[u] = idx >> 4; vq8[u] = (idx & 15) * 8;
        pv[u] = *(const uint4*)&Vg[(size_t)vrow[u] * NPIX + vq8[u]];
    }
    __syncthreads();

    float accO[2][4][4];
    #pragma unroll
    for (int mt = 0; mt < 2; mt++)
        #pragma unroll
        for (int nt = 0; nt < 4; nt++)
            #pragma unroll
            for (int r = 0; r < 4; r++) accO[mt][nt][r] = 0.f;
    float s[2][2] = {{0.f, 0.f}, {0.f, 0.f}};

    #pragma unroll 1
    for (int jt = 0; jt < 8; jt++) {
        // logits: 64 x 128, K=40 (tf32). Warp: m32 (2 x m16) x n16 (2 x n8)
        float accS[2][2][4];
        #pragma unroll
        for (int mt = 0; mt < 2; mt++)
            #pragma unroll
            for (int nt = 0; nt < 2; nt++)
                #pragma unroll
                for (int r = 0; r < 4; r++) accS[mt][nt][r] = 0.f;
        #pragma unroll
        for (int k = 0; k < 5; k++) {
            int kk = k * 8;
            uint32_t af[2][4];
            #pragma unroll
            for (int mt = 0; mt < 2; mt++) {
                int abase = (wq * 32 + mt * 16 + g) * ASTR2 + kk + tg;
                af[mt][0] = __float_as_uint(Qs[abase]);
                af[mt][1] = __float_as_uint(Qs[abase + 8 * ASTR2]);
                af[mt][2] = __float_as_uint(Qs[abase + 4]);
                af[mt][3] = __float_as_uint(Qs[abase + 8 * ASTR2 + 4]);
            }
            #pragma unroll
            for (int nt = 0; nt < 2; nt++) {
                uint32_t bf[2];
                int bb = (wr * 16 + nt * 8 + g) * ASTR2 + kk + tg;
                bf[0] = __float_as_uint(Ks[bb]);
                bf[1] = __float_as_uint(Ks[bb + 4]);
                #pragma unroll
                for (int mt = 0; mt < 2; mt++)
                    mma_tf32(accS[mt][nt], af[mt], bf);
            }
        }

        // exp + rowsum + write Ps (bf16 pairs)
        #pragma unroll
        for (int mt = 0; mt < 2; mt++) {
            int r0l = wq * 32 + mt * 16 + g;
            #pragma unroll
            for (int nt = 0; nt < 2; nt++) {
                float e0 = __expf(accS[mt][nt][0]);
                float e1 = __expf(accS[mt][nt][1]);
                float e2 = __expf(accS[mt][nt][2]);
                float e3 = __expf(accS[mt][nt][3]);
                s[mt][0] += e0 + e1; s[mt][1] += e2 + e3;
                int c = wr * 16 + nt * 8 + 2 * tg;
                *(__nv_bfloat162*)&PsH[r0l * PSTRH + c]       = __floats2bfloat162_rn(e0, e1);
                *(__nv_bfloat162*)&PsH[(r0l + 8) * PSTRH + c] = __floats2bfloat162_rn(e2, e3);
            }
        }

        // store prefetched V tile into buffer jt&1
        __nv_bfloat16* Vcur = VsH + (jt & 1) * VS_ELEMS;
        #pragma unroll
        for (int u = 0; u < 8; u++)
            *(uint4*)&Vcur[vrow[u] * PSTRH + vq8[u]] = pv[u];

        __syncthreads();   // Ps + Vs(jt) visible; all logits reads of Ks done

        // AV: 64 x 256 += Ps(64x128) @ Vs(256x128)^T, bf16 k16, ldmatrix frags
        uint32_t voff = (uint32_t)((jt & 1) * VS_ELEMS * 2);
        #pragma unroll
        for (int kk = 0; kk < 128; kk += 16) {
            uint32_t af[2][4];
            ldmatrix_x4(af[0][0], af[0][1], af[0][2], af[0][3], psA[0] + kk * 2);
            ldmatrix_x4(af[1][0], af[1][1], af[1][2], af[1][3], psA[1] + kk * 2);
            #pragma unroll
            for (int nt2 = 0; nt2 < 2; nt2++) {
                uint32_t b0, b1, b2, b3;
                ldmatrix_x4(b0, b1, b2, b3, vsB[nt2] + voff + kk * 2);
                uint32_t bfe[2] = {b0, b1};
                uint32_t bfo[2] = {b2, b3};
                #pragma unroll
                for (int mt = 0; mt < 2; mt++) {
                    mma_bf16(accO[mt][nt2 * 2 + 0], af[mt], bfe);
                    mma_bf16(accO[mt][nt2 * 2 + 1], af[mt], bfo);
                }
            }
        }

        // overlap with AV: restage Ks(jt+1), prefetch V(jt+1)
        if (jt < 7) {
            int j1 = (jt + 1) * JT;
            for (int idx = tid; idx < 1280; idx += 512) {
                int row = idx / 10, c4 = (idx % 10) * 4;
                *(float4*)&Ks[row * ASTR2 + c4] =
                    *(const float4*)&kab[(size_t)(j1 + row) * ASTR2 + c4];
            }
            #pragma unroll
            for (int u = 0; u < 8; u++)
                pv[u] = *(const uint4*)&Vg[(size_t)vrow[u] * NPIX + j1 + vq8[u]];
        }
        __syncthreads();   // Ks(jt+1) visible; AV reads of Ps done before next exp
    }

    // finalize row sums: reduce tg lanes, accumulate across wr warps
    #pragma unroll
    for (int mt = 0; mt < 2; mt++)
        #pragma unroll
        for (int h = 0; h < 2; h++) {
            float v = s[mt][h];
            v += __shfl_xor_sync(0xffffffffu, v, 1);
            v += __shfl_xor_sync(0xffffffffu, v, 2);
            if (tg == 0) atomicAdd(&rs[wq * 32 + mt * 16 + h * 8 + g], v);
        }
    __syncthreads();
    if (tid < IB) ri[tid] = gamma[0] / rs[tid];
    __syncthreads();

    // epilogue: out[b,c,i] = ri[i] * acc + x[b,c,i]
    #pragma unroll
    for (int mt = 0; mt < 2; mt++) {
        int r0l = wq * 32 + mt * 16 + g;
        float inv0 = ri[r0l], inv1 = ri[r0l + 8];
        #pragma unroll
        for (int nt = 0; nt < 4; nt++) {
            int ch = wr * 32 + nt * 8 + 2 * tg;
            size_t b0 = ((size_t)b * CCH + ch) * NPIX + i0 + r0l;
            size_t b1 = b0 + NPIX;                 // ch+1
            out[b0]     = accO[mt][nt][0] * inv0 + x[b0];
            out[b1]     = accO[mt][nt][1] * inv0 + x[b1];
            out[b0 + 8] = accO[mt][nt][2] * inv1 + x[b0 + 8];
            out[b1 + 8] = accO[mt][nt][3] * inv1 + x[b1 + 8];
        }
    }
}

// ---------------------------------------------------------------------------
extern "C" void kernel_launch(void* const* d_in, const int* in_sizes, int n_in,
                              void* d_out, int out_size) {
    const float* x     = (const float*)d_in[0];
    const float* Wq    = (const float*)d_in[1];
    const float* bq    = (const float*)d_in[2];
    const float* Wk    = (const float*)d_in[3];
    const float* bk    = (const float*)d_in[4];
    const float* Wv    = (const float*)d_in[5];
    const float* bv    = (const float*)d_in[6];
    const float* Wr    = (const float*)d_in[7];
    const float* gamma = (const float*)d_in[9];
    float* out = (float*)d_out;

    cudaFuncSetAttribute(proj_gemm_mma, cudaFuncAttributeMaxDynamicSharedMemorySize, PROJ_SMEM);
    cudaFuncSetAttribute(fused_attn, cudaFuncAttributeMaxDynamicSharedMemorySize, FUSED_SMEM);

    proj_gemm_mma<<<dim3(NPIX / BN_P, 3, BATCH), 512, PROJ_SMEM>>>(x, Wq, bq, Wk, bk, Wv, bv, Wr);
    fused_attn<<<dim3(NPIX / IB, BATCH), 512, FUSED_SMEM>>>(x, gamma, out);
}

// round 16
// speedup vs baseline: 1.0965x; 1.0965x over previous
#include <cuda_runtime.h>
#include <cuda_bf16.h>
#include <math.h>
#include <cstdint>

// Problem constants
#define BATCH 8
#define CCH   256
#define NPIX  1024
#define DHEAD 32
#define OC_ALL 320          // 32 q + 32 k + 256 v
#define KA    40            // augmented K padded to 40 (34 used)
#define ASTR2 44            // row stride for q'/k' (conflict-free tf32 frags)

// Scratch (device globals)
__device__ __nv_bfloat16 g_Vb[BATCH * CCH * NPIX];       // V projections, bf16
__device__ float g_qa[BATCH * NPIX * ASTR2];             // augmented scaled q rows (tf32)
__device__ float g_ka[BATCH * NPIX * ASTR2];             // augmented k rows (tf32)

// ===========================================================================
// helpers
// ===========================================================================
__device__ __forceinline__ float f2tf32(float f) {
    uint32_t u;
    asm("cvt.rna.tf32.f32 %0, %1;" : "=r"(u) : "f"(f));
    return __uint_as_float(u);
}
__device__ __forceinline__ float4 cvt4(float4 v) {
    v.x = f2tf32(v.x); v.y = f2tf32(v.y); v.z = f2tf32(v.z); v.w = f2tf32(v.w);
    return v;
}
__device__ __forceinline__ void mma_tf32(float* d, const uint32_t* a, const uint32_t* b) {
    asm volatile(
        "mma.sync.aligned.m16n8k8.row.col.f32.tf32.tf32.f32 "
        "{%0,%1,%2,%3}, {%4,%5,%6,%7}, {%8,%9}, {%0,%1,%2,%3};\n"
        : "+f"(d[0]), "+f"(d[1]), "+f"(d[2]), "+f"(d[3])
        : "r"(a[0]), "r"(a[1]), "r"(a[2]), "r"(a[3]), "r"(b[0]), "r"(b[1]));
}
__device__ __forceinline__ void mma_bf16(float* d, const uint32_t* a, const uint32_t* b) {
    asm volatile(
        "mma.sync.aligned.m16n8k16.row.col.f32.bf16.bf16.f32 "
        "{%0,%1,%2,%3}, {%4,%5,%6,%7}, {%8,%9}, {%0,%1,%2,%3};\n"
        : "+f"(d[0]), "+f"(d[1]), "+f"(d[2]), "+f"(d[3])
        : "r"(a[0]), "r"(a[1]), "r"(a[2]), "r"(a[3]), "r"(b[0]), "r"(b[1]));
}
__device__ __forceinline__ void ldmatrix_x4(uint32_t& r0, uint32_t& r1, uint32_t& r2,
                                            uint32_t& r3, uint32_t addr) {
    asm volatile("ldmatrix.sync.aligned.m8n8.x4.shared.b16 {%0,%1,%2,%3}, [%4];"
        : "=r"(r0), "=r"(r1), "=r"(r2), "=r"(r3) : "r"(addr));
}
__device__ __forceinline__ void cp_async16(uint32_t dst, const void* src) {
    asm volatile("cp.async.cg.shared.global [%0], [%1], 16;"
        :: "r"(dst), "l"(src) : "memory");
}
__device__ __forceinline__ void cp_async_commit() {
    asm volatile("cp.async.commit_group;" ::: "memory");
}
__device__ __forceinline__ void cp_async_wait0() {
    asm volatile("cp.async.wait_group 0;" ::: "memory");
}

// ---------------------------------------------------------------------------
// 1) Projection GEMM (tf32 mma) — round-14 config (known best), 256 threads,
//    tile 128m x 128n: q,k -> smem -> augmented g_qa/g_ka; v -> g_Vb (bf16)
// ---------------------------------------------------------------------------
#define ASTR 36
#define BSTR_P 136
#define QK_LD 132
#define PROJ_SMEM ((2 * 128 * ASTR + 2 * 32 * BSTR_P) * (int)sizeof(float))   // 71680

__global__ __launch_bounds__(256) void proj_gemm_mma(const float* __restrict__ x,
                                                     const float* __restrict__ Wq,
                                                     const float* __restrict__ bq,
                                                     const float* __restrict__ Wk,
                                                     const float* __restrict__ bk,
                                                     const float* __restrict__ Wv,
                                                     const float* __restrict__ bv,
                                                     const float* __restrict__ Wr) {
    int b  = blockIdx.z;
    int m0 = blockIdx.y * 128;
    int n0 = blockIdx.x * 128;
    const float* X = x + (size_t)b * CCH * NPIX;

    extern __shared__ float sm[];
    float* As = sm;
    float* Bs = sm + 2 * 128 * ASTR;

    int tid = threadIdx.x, warp = tid >> 5, lane = tid & 31;
    int wm = warp >> 2, wn = warp & 3;
    int g = lane >> 2, tg = lane & 3;

    float acc[4][4][4];
    #pragma unroll
    for (int i = 0; i < 4; i++)
        #pragma unroll
        for (int j = 0; j < 4; j++)
            #pragma unroll
            for (int r = 0; r < 4; r++) acc[i][j][r] = 0.f;

    int arow[4], akq[4], brow[4], bnq[4];
    const float* wbase[4];
    #pragma unroll
    for (int u = 0; u < 4; u++) {
        int idx = tid + u * 256;
        arow[u] = idx >> 3;  akq[u] = (idx & 7) * 4;
        brow[u] = idx >> 5;  bnq[u] = (idx & 31) * 4;
        int r = m0 + arow[u];
        if (r < 32)       wbase[u] = Wq + (size_t)r * CCH;
        else if (r < 64)  wbase[u] = Wk + (size_t)(r - 32) * CCH;
        else if (r < 320) wbase[u] = Wv + (size_t)(r - 64) * CCH;
        else              wbase[u] = nullptr;
    }

    float4 pa[4], pb[4];
    #pragma unroll
    for (int u = 0; u < 4; u++) {
        pa[u] = wbase[u] ? *(const float4*)&wbase[u][akq[u]] : make_float4(0.f, 0.f, 0.f, 0.f);
        pb[u] = *(const float4*)&X[(size_t)brow[u] * NPIX + n0 + bnq[u]];
    }
    #pragma unroll
    for (int u = 0; u < 4; u++) {
        *(float4*)&As[arow[u] * ASTR + akq[u]]   = cvt4(pa[u]);
        *(float4*)&Bs[brow[u] * BSTR_P + bnq[u]] = cvt4(pb[u]);
    }
    __syncthreads();

    #pragma unroll 1
    for (int t = 0; t < 8; t++) {
        if (t < 7) {
            int k0 = (t + 1) * 32;
            #pragma unroll
            for (int u = 0; u < 4; u++) {
                pa[u] = wbase[u] ? *(const float4*)&wbase[u][k0 + akq[u]]
                                 : make_float4(0.f, 0.f, 0.f, 0.f);
                pb[u] = *(const float4*)&X[(size_t)(k0 + brow[u]) * NPIX + n0 + bnq[u]];
            }
        }
        const float* A = As + (t & 1) * 128 * ASTR;
        const float* B = Bs + (t & 1) * 32 * BSTR_P;
        #pragma unroll
        for (int kk = 0; kk < 32; kk += 8) {
            uint32_t af[4][4], bf[4][2];
            #pragma unroll
            for (int mt = 0; mt < 4; mt++) {
                int r = wm * 64 + mt * 16 + g;
                af[mt][0] = __float_as_uint(A[r * ASTR + kk + tg]);
                af[mt][1] = __float_as_uint(A[(r + 8) * ASTR + kk + tg]);
                af[mt][2] = __float_as_uint(A[r * ASTR + kk + tg + 4]);
                af[mt][3] = __float_as_uint(A[(r + 8) * ASTR + kk + tg + 4]);
            }
            #pragma unroll
            for (int nt = 0; nt < 4; nt++) {
                int nc = wn * 32 + nt * 8 + g;
                bf[nt][0] = __float_as_uint(B[(kk + tg) * BSTR_P + nc]);
                bf[nt][1] = __float_as_uint(B[(kk + tg + 4) * BSTR_P + nc]);
            }
            #pragma unroll
            for (int mt = 0; mt < 4; mt++)
                #pragma unroll
                for (int nt = 0; nt < 4; nt++)
                    mma_tf32(acc[mt][nt], af[mt], bf[nt]);
        }
        if (t < 7) {
            float* An = As + ((t + 1) & 1) * 128 * ASTR;
            float* Bn = Bs + ((t + 1) & 1) * 32 * BSTR_P;
            #pragma unroll
            for (int u = 0; u < 4; u++) {
                *(float4*)&An[arow[u] * ASTR + akq[u]]   = cvt4(pa[u]);
                *(float4*)&Bn[brow[u] * BSTR_P + bnq[u]] = cvt4(pb[u]);
            }
        }
        __syncthreads();
    }

    // epilogue: q,k rows (<64) -> smem QKs; v rows -> g_Vb bf16
    float* QKs = sm;   // reuse (64 x 132 floats = 33792 < 71680)
    #pragma unroll
    for (int mt = 0; mt < 4; mt++) {
        int rbase = m0 + wm * 64 + mt * 16 + g;
        #pragma unroll
        for (int half = 0; half < 2; half++) {
            int r = rbase + half * 8;
            if (r >= OC_ALL) continue;
            float bias = (r < 32) ? bq[r] : (r < 64) ? bk[r - 32] : bv[r - 64];
            #pragma unroll
            for (int nt = 0; nt < 4; nt++) {
                int cl = wn * 32 + nt * 8 + 2 * tg;
                float v0 = acc[mt][nt][half * 2 + 0] + bias;
                float v1 = acc[mt][nt][half * 2 + 1] + bias;
                if (r < 64) {
                    QKs[r * QK_LD + cl]     = v0;
                    QKs[r * QK_LD + cl + 1] = v1;
                } else {
                    *(__nv_bfloat162*)&g_Vb[((size_t)b * CCH + (r - 64)) * NPIX + n0 + cl] =
                        __floats2bfloat162_rn(v0, v1);
                }
            }
        }
    }
    if (m0 != 0) return;
    __syncthreads();

    // augment (m-tile 0 only): 128 threads, one pixel each
    if (tid < 128) {
        int n = n0 + tid;
        float a0 = 0.f, a1 = 0.f;
        float q[DHEAD];
        #pragma unroll
        for (int d = 0; d < DHEAD; d++) {
            q[d] = QKs[d * QK_LD + tid];
            a0 += q[d] * Wr[2 * d];
            a1 += q[d] * Wr[2 * d + 1];
        }
        const float scale = rsqrtf((float)DHEAD);
        float* qrow = g_qa + (size_t)(b * NPIX + n) * ASTR2;
        #pragma unroll
        for (int d = 0; d < DHEAD; d++) qrow[d] = f2tf32(q[d] * scale);
        qrow[32] = f2tf32(a0 * scale);
        qrow[33] = f2tf32(a1 * scale);
        #pragma unroll
        for (int d = 34; d < KA; d++) qrow[d] = 0.f;

        float* krow = g_ka + (size_t)(b * NPIX + n) * ASTR2;
        #pragma unroll
        for (int d = 0; d < DHEAD; d++) krow[d] = f2tf32(QKs[(32 + d) * QK_LD + tid]);
        int hi = n >> 5, wi = n & 31;
        krow[32] = f2tf32(-(float)hi * (1.f / 31.f));
        krow[33] = f2tf32(-(float)wi * (1.f / 31.f));
        #pragma unroll
        for (int d = 34; d < KA; d++) krow[d] = 0.f;
    }
}

// ---------------------------------------------------------------------------
// 2) Fused attention: cp.async double-buffered Ks and Vs staging.
//    CTA = (64 i-rows, batch), 512 threads; warp grid 2(i) x 8(j/ch).
//    Copies for jt+1 issued at top of body, drain across logits+exp+AV.
// ---------------------------------------------------------------------------
#define IB 64
#define JT 128
#define PSTRH 136
#define KSZ (128 * ASTR2 * 4)                   // 22528 B per Ks buffer
#define VSZ (CCH * PSTRH * 2)                   // 69632 B per Vs buffer
// byte offsets in dynamic smem
#define QS_B 0
#define KS_B (QS_B + IB * ASTR2 * 4)            // 11264
#define PS_B (KS_B + 2 * KSZ)                   // 56320
#define VS_B (PS_B + IB * PSTRH * 2)            // 73728
#define RS_B (VS_B + 2 * VSZ)                   // 212992
#define RI_B (RS_B + IB * 4)
#define FUSED_SMEM (RI_B + IB * 4)              // 213504

__global__ __launch_bounds__(512) void fused_attn(const float* __restrict__ x,
                                                  const float* __restrict__ gamma,
                                                  float* __restrict__ out) {
    int b  = blockIdx.y;
    int i0 = blockIdx.x * IB;
    const float* qab = g_qa + (size_t)b * NPIX * ASTR2;
    const float* kab = g_ka + (size_t)b * NPIX * ASTR2;
    const __nv_bfloat16* Vg = g_Vb + (size_t)b * CCH * NPIX;

    extern __shared__ char smc[];
    float* Qs = (float*)(smc + QS_B);
    __nv_bfloat16* PsH = (__nv_bfloat16*)(smc + PS_B);
    float* rs = (float*)(smc + RS_B);
    float* ri = (float*)(smc + RI_B);
    uint32_t smem_u = (uint32_t)__cvta_generic_to_shared(smc);

    int tid = threadIdx.x, warp = tid >> 5, lane = tid & 31;
    int wq = warp >> 3, wr = warp & 7;          // 2 (i) x 8 (j/ch) warp grid
    int g = lane >> 2, tg = lane & 3;

    // ldmatrix lane addresses (byte, shared space)
    uint32_t psA[2], vsB[2];
    {
        int sub = lane & 7;
        int ar = wq * 32 + ((lane >> 3) & 1) * 8 + sub;   // A: row
        int ac = (lane >> 4) * 8;                         // A: col (k)
        psA[0] = smem_u + PS_B + (uint32_t)(ar * PSTRH + ac) * 2;
        psA[1] = psA[0] + 16 * PSTRH * 2;
        int br = wr * 32 + (lane >> 4) * 8 + sub;         // B: row (channel)
        int bc = ((lane >> 3) & 1) * 8;                   // B: col (k)
        vsB[0] = smem_u + VS_B + (uint32_t)(br * PSTRH + bc) * 2;
        vsB[1] = vsB[0] + 16 * PSTRH * 2;
    }

    if (tid < IB) rs[tid] = 0.f;

    // staging index precompute
    int krow_[3], kc4_[3];                      // Ks: 1280 float4 chunks
    #pragma unroll
    for (int u = 0; u < 3; u++) {
        int idx = tid + u * 512;
        krow_[u] = idx / 10; kc4_[u] = (idx % 10) * 4;
    }
    int vrow_[8], vq8_[8];                      // Vs: 4096 16B chunks
    #pragma unroll
    for (int u = 0; u < 8; u++) {
        int idx = tid + u * 512;
        vrow_[u] = idx >> 4; vq8_[u] = (idx & 15) * 8;
    }

    // prologue: stage Qs (regular), cp.async Ks(0) + V(0)
    for (int idx = tid; idx < 640; idx += 512) {
        int row = idx / 10, c4 = (idx % 10) * 4;
        *(float4*)&Qs[row * ASTR2 + c4] = *(const float4*)&qab[(size_t)(i0 + row) * ASTR2 + c4];
    }
    #pragma unroll
    for (int u = 0; u < 3; u++) {
        if (u < 2 || tid < 256) {
            uint32_t dst = smem_u + KS_B + (uint32_t)(krow_[u] * ASTR2 + kc4_[u]) * 4;
            cp_async16(dst, &kab[(size_t)krow_[u] * ASTR2 + kc4_[u]]);
        }
    }
    #pragma unroll
    for (int u = 0; u < 8; u++) {
        uint32_t dst = smem_u + VS_B + (uint32_t)(vrow_[u] * PSTRH + vq8_[u]) * 2;
        cp_async16(dst, &Vg[(size_t)vrow_[u] * NPIX + vq8_[u]]);
    }
    cp_async_commit();
    cp_async_wait0();
    __syncthreads();

    float accO[2][4][4];
    #pragma unroll
    for (int mt = 0; mt < 2; mt++)
        #pragma unroll
        for (int nt = 0; nt < 4; nt++)
            #pragma unroll
            for (int r = 0; r < 4; r++) accO[mt][nt][r] = 0.f;
    float s[2][2] = {{0.f, 0.f}, {0.f, 0.f}};

    #pragma unroll 1
    for (int jt = 0; jt < 8; jt++) {
        // issue next-tile copies first; they drain across logits+exp+AV
        if (jt < 7) {
            int j1 = (jt + 1) * JT;
            uint32_t kbase = smem_u + KS_B + (uint32_t)(((jt + 1) & 1) * KSZ);
            #pragma unroll
            for (int u = 0; u < 3; u++) {
                if (u < 2 || tid < 256) {
                    uint32_t dst = kbase + (uint32_t)(krow_[u] * ASTR2 + kc4_[u]) * 4;
                    cp_async16(dst, &kab[(size_t)(j1 + krow_[u]) * ASTR2 + kc4_[u]]);
                }
            }
            uint32_t vbase = smem_u + VS_B + (uint32_t)(((jt + 1) & 1) * VSZ);
            #pragma unroll
            for (int u = 0; u < 8; u++) {
                uint32_t dst = vbase + (uint32_t)(vrow_[u] * PSTRH + vq8_[u]) * 2;
                cp_async16(dst, &Vg[(size_t)vrow_[u] * NPIX + j1 + vq8_[u]]);
            }
            cp_async_commit();
        }

        // logits: 64 x 128, K=40 (tf32). Warp: m32 (2 x m16) x n16 (2 x n8)
        const float* Kcur = (const float*)(smc + KS_B + (jt & 1) * KSZ);
        float accS[2][2][4];
        #pragma unroll
        for (int mt = 0; mt < 2; mt++)
            #pragma unroll
            for (int nt = 0; nt < 2; nt++)
                #pragma unroll
                for (int r = 0; r < 4; r++) accS[mt][nt][r] = 0.f;
        #pragma unroll
        for (int k = 0; k < 5; k++) {
            int kk = k * 8;
            uint32_t af[2][4];
            #pragma unroll
            for (int mt = 0; mt < 2; mt++) {
                int abase = (wq * 32 + mt * 16 + g) * ASTR2 + kk + tg;
                af[mt][0] = __float_as_uint(Qs[abase]);
                af[mt][1] = __float_as_uint(Qs[abase + 8 * ASTR2]);
                af[mt][2] = __float_as_uint(Qs[abase + 4]);
                af[mt][3] = __float_as_uint(Qs[abase + 8 * ASTR2 + 4]);
            }
            #pragma unroll
            for (int nt = 0; nt < 2; nt++) {
                uint32_t bf[2];
                int bb = (wr * 16 + nt * 8 + g) * ASTR2 + kk + tg;
                bf[0] = __float_as_uint(Kcur[bb]);
                bf[1] = __float_as_uint(Kcur[bb + 4]);
                #pragma unroll
                for (int mt = 0; mt < 2; mt++)
                    mma_tf32(accS[mt][nt], af[mt], bf);
            }
        }

        // exp + rowsum + write Ps (bf16 pairs)
        #pragma unroll
        for (int mt = 0; mt < 2; mt++) {
            int r0l = wq * 32 + mt * 16 + g;
            #pragma unroll
            for (int nt = 0; nt < 2; nt++) {
                float e0 = __expf(accS[mt][nt][0]);
                float e1 = __expf(accS[mt][nt][1]);
                float e2 = __expf(accS[mt][nt][2]);
                float e3 = __expf(accS[mt][nt][3]);
                s[mt][0] += e0 + e1; s[mt][1] += e2 + e3;
                int c = wr * 16 + nt * 8 + 2 * tg;
                *(__nv_bfloat162*)&PsH[r0l * PSTRH + c]       = __floats2bfloat162_rn(e0, e1);
                *(__nv_bfloat162*)&PsH[(r0l + 8) * PSTRH + c] = __floats2bfloat162_rn(e2, e3);
            }
        }
        __syncthreads();   // Ps visible (Vs(jt) already complete since prev iter)

        // AV: 64 x 256 += Ps(64x128) @ Vs(256x128)^T, bf16 k16, ldmatrix frags
        uint32_t voff = (uint32_t)((jt & 1) * VSZ);
        #pragma unroll
        for (int kk = 0; kk < 128; kk += 16) {
            uint32_t af[2][4];
            ldmatrix_x4(af[0][0], af[0][1], af[0][2], af[0][3], psA[0] + kk * 2);
            ldmatrix_x4(af[1][0], af[1][1], af[1][2], af[1][3], psA[1] + kk * 2);
            #pragma unroll
            for (int nt2 = 0; nt2 < 2; nt2++) {
                uint32_t b0, b1, b2, b3;
                ldmatrix_x4(b0, b1, b2, b3, vsB[nt2] + voff + kk * 2);
                uint32_t bfe[2] = {b0, b1};
                uint32_t bfo[2] = {b2, b3};
                #pragma unroll
                for (int mt = 0; mt < 2; mt++) {
                    mma_bf16(accO[mt][nt2 * 2 + 0], af[mt], bfe);
                    mma_bf16(accO[mt][nt2 * 2 + 1], af[mt], bfo);
                }
            }
        }

        cp_async_wait0();  // Ks(jt+1)+Vs(jt+1) arrived
        __syncthreads();   // all AV reads of Ps/Vs done before next exp/copies
    }

    // finalize row sums: reduce tg lanes, accumulate across wr warps
    #pragma unroll
    for (int mt = 0; mt < 2; mt++)
        #pragma unroll
        for (int h = 0; h < 2; h++) {
            float v = s[mt][h];
            v += __shfl_xor_sync(0xffffffffu, v, 1);
            v += __shfl_xor_sync(0xffffffffu, v, 2);
            if (tg == 0) atomicAdd(&rs[wq * 32 + mt * 16 + h * 8 + g], v);
        }
    __syncthreads();
    if (tid < IB) ri[tid] = gamma[0] / rs[tid];
    __syncthreads();

    // epilogue: out[b,c,i] = ri[i] * acc + x[b,c,i]
    #pragma unroll
    for (int mt = 0; mt < 2; mt++) {
        int r0l = wq * 32 + mt * 16 + g;
        float inv0 = ri[r0l], inv1 = ri[r0l + 8];
        #pragma unroll
        for (int nt = 0; nt < 4; nt++) {
            int ch = wr * 32 + nt * 8 + 2 * tg;
            size_t b0 = ((size_t)b * CCH + ch) * NPIX + i0 + r0l;
            size_t b1 = b0 + NPIX;                 // ch+1
            out[b0]     = accO[mt][nt][0] * inv0 + x[b0];
            out[b1]     = accO[mt][nt][1] * inv0 + x[b1];
            out[b0 + 8] = accO[mt][nt][2] * inv1 + x[b0 + 8];
            out[b1 + 8] = accO[mt][nt][3] * inv1 + x[b1 + 8];
        }
    }
}

// ---------------------------------------------------------------------------
extern "C" void kernel_launch(void* const* d_in, const int* in_sizes, int n_in,
                              void* d_out, int out_size) {
    const float* x     = (const float*)d_in[0];
    const float* Wq    = (const float*)d_in[1];
    const float* bq    = (const float*)d_in[2];
    const float* Wk    = (const float*)d_in[3];
    const float* bk    = (const float*)d_in[4];
    const float* Wv    = (const float*)d_in[5];
    const float* bv    = (const float*)d_in[6];
    const float* Wr    = (const float*)d_in[7];
    const float* gamma = (const float*)d_in[9];
    float* out = (float*)d_out;

    cudaFuncSetAttribute(proj_gemm_mma, cudaFuncAttributeMaxDynamicSharedMemorySize, PROJ_SMEM);
    cudaFuncSetAttribute(fused_attn, cudaFuncAttributeMaxDynamicSharedMemorySize, FUSED_SMEM);

    proj_gemm_mma<<<dim3(NPIX / 128, 3, BATCH), 256, PROJ_SMEM>>>(x, Wq, bq, Wk, bk, Wv, bv, Wr);
    fused_attn<<<dim3(NPIX / IB, BATCH), 512, FUSED_SMEM>>>(x, gamma, out);
}

// round 17
// speedup vs baseline: 1.1322x; 1.0325x over previous
#include <cuda_runtime.h>
#include <cuda_bf16.h>
#include <math.h>
#include <cstdint>

// Problem constants
#define BATCH 8
#define CCH   256
#define NPIX  1024
#define DHEAD 32
#define OC_ALL 320          // 32 q + 32 k + 256 v
#define KA    40            // augmented K padded to 40 (34 used)
#define ASTR2 44            // row stride for q'/k' (conflict-free tf32 frags)

// Scratch (device globals)
__device__ __nv_bfloat16 g_Vb[BATCH * CCH * NPIX];       // V projections, bf16
__device__ float g_qa[BATCH * NPIX * ASTR2];             // augmented scaled q rows (tf32)
__device__ float g_ka[BATCH * NPIX * ASTR2];             // augmented k rows (tf32)

// ===========================================================================
// helpers
// ===========================================================================
__device__ __forceinline__ float f2tf32(float f) {
    uint32_t u;
    asm("cvt.rna.tf32.f32 %0, %1;" : "=r"(u) : "f"(f));
    return __uint_as_float(u);
}
__device__ __forceinline__ void mma_tf32(float* d, const uint32_t* a, const uint32_t* b) {
    asm volatile(
        "mma.sync.aligned.m16n8k8.row.col.f32.tf32.tf32.f32 "
        "{%0,%1,%2,%3}, {%4,%5,%6,%7}, {%8,%9}, {%0,%1,%2,%3};\n"
        : "+f"(d[0]), "+f"(d[1]), "+f"(d[2]), "+f"(d[3])
        : "r"(a[0]), "r"(a[1]), "r"(a[2]), "r"(a[3]), "r"(b[0]), "r"(b[1]));
}
__device__ __forceinline__ void mma_bf16(float* d, const uint32_t* a, const uint32_t* b) {
    asm volatile(
        "mma.sync.aligned.m16n8k16.row.col.f32.bf16.bf16.f32 "
        "{%0,%1,%2,%3}, {%4,%5,%6,%7}, {%8,%9}, {%0,%1,%2,%3};\n"
        : "+f"(d[0]), "+f"(d[1]), "+f"(d[2]), "+f"(d[3])
        : "r"(a[0]), "r"(a[1]), "r"(a[2]), "r"(a[3]), "r"(b[0]), "r"(b[1]));
}
__device__ __forceinline__ void ldmatrix_x4(uint32_t& r0, uint32_t& r1, uint32_t& r2,
                                            uint32_t& r3, uint32_t addr) {
    asm volatile("ldmatrix.sync.aligned.m8n8.x4.shared.b16 {%0,%1,%2,%3}, [%4];"
        : "=r"(r0), "=r"(r1), "=r"(r2), "=r"(r3) : "r"(addr));
}
__device__ __forceinline__ void cp_async16(uint32_t dst, const void* src) {
    asm volatile("cp.async.cg.shared.global [%0], [%1], 16;"
        :: "r"(dst), "l"(src) : "memory");
}
__device__ __forceinline__ void cp_async16z(uint32_t dst, const void* src, int src_size) {
    asm volatile("cp.async.cg.shared.global [%0], [%1], 16, %2;"
        :: "r"(dst), "l"(src), "r"(src_size) : "memory");
}
__device__ __forceinline__ void cp_async_commit() {
    asm volatile("cp.async.commit_group;" ::: "memory");
}
__device__ __forceinline__ void cp_async_wait0() {
    asm volatile("cp.async.wait_group 0;" ::: "memory");
}
__device__ __forceinline__ void cp_async_wait1() {
    asm volatile("cp.async.wait_group 1;" ::: "memory");
}

// ---------------------------------------------------------------------------
// 1) Projection GEMM (tf32 mma), cp.async staged, 256 threads, 128m x 128n:
//    q,k -> smem -> augmented g_qa/g_ka; v -> g_Vb (bf16)
//    Operands staged raw fp32 (HW tf32 truncation; logits inputs re-rounded
//    RNA in augment, so logits accuracy unchanged).
// ---------------------------------------------------------------------------
#define ASTR 36
#define BSTR_P 136
#define QK_LD 132
#define PROJ_SMEM ((2 * 128 * ASTR + 2 * 32 * BSTR_P) * (int)sizeof(float))   // 71680

__global__ __launch_bounds__(256) void proj_gemm_mma(const float* __restrict__ x,
                                                     const float* __restrict__ Wq,
                                                     const float* __restrict__ bq,
                                                     const float* __restrict__ Wk,
                                                     const float* __restrict__ bk,
                                                     const float* __restrict__ Wv,
                                                     const float* __restrict__ bv,
                                                     const float* __restrict__ Wr) {
    int b  = blockIdx.z;
    int m0 = blockIdx.y * 128;
    int n0 = blockIdx.x * 128;
    const float* X = x + (size_t)b * CCH * NPIX;

    extern __shared__ float sm[];
    float* As = sm;
    float* Bs = sm + 2 * 128 * ASTR;
    uint32_t smem_u = (uint32_t)__cvta_generic_to_shared(sm);
    const uint32_t AS_U = smem_u;
    const uint32_t BS_U = smem_u + 2u * 128 * ASTR * 4;

    int tid = threadIdx.x, warp = tid >> 5, lane = tid & 31;
    int wm = warp >> 2, wn = warp & 3;
    int g = lane >> 2, tg = lane & 3;

    float acc[4][4][4];
    #pragma unroll
    for (int i = 0; i < 4; i++)
        #pragma unroll
        for (int j = 0; j < 4; j++)
            #pragma unroll
            for (int r = 0; r < 4; r++) acc[i][j][r] = 0.f;

    int arow[4], akq[4], brow[4], bnq[4];
    const float* wbase[4];
    int wsz[4];
    #pragma unroll
    for (int u = 0; u < 4; u++) {
        int idx = tid + u * 256;
        arow[u] = idx >> 3;  akq[u] = (idx & 7) * 4;
        brow[u] = idx >> 5;  bnq[u] = (idx & 31) * 4;
        int r = m0 + arow[u];
        if (r < 32)       { wbase[u] = Wq + (size_t)r * CCH;        wsz[u] = 16; }
        else if (r < 64)  { wbase[u] = Wk + (size_t)(r - 32) * CCH; wsz[u] = 16; }
        else if (r < 320) { wbase[u] = Wv + (size_t)(r - 64) * CCH; wsz[u] = 16; }
        else              { wbase[u] = Wq;                          wsz[u] = 0;  }
    }

    // issue chunk 0 and chunk 1 copies
    #pragma unroll
    for (int t0 = 0; t0 < 2; t0++) {
        uint32_t abase = AS_U + (uint32_t)(t0 * 128 * ASTR * 4);
        uint32_t bbase = BS_U + (uint32_t)(t0 * 32 * BSTR_P * 4);
        int k0 = t0 * 32;
        #pragma unroll
        for (int u = 0; u < 4; u++) {
            cp_async16z(abase + (uint32_t)(arow[u] * ASTR + akq[u]) * 4,
                        &wbase[u][k0 + akq[u]], wsz[u]);
            cp_async16(bbase + (uint32_t)(brow[u] * BSTR_P + bnq[u]) * 4,
                       &X[(size_t)(k0 + brow[u]) * NPIX + n0 + bnq[u]]);
        }
        cp_async_commit();
    }

    #pragma unroll 1
    for (int t = 0; t < 8; t++) {
        if (t < 7) cp_async_wait1(); else cp_async_wait0();
        __syncthreads();

        const float* A = As + (t & 1) * 128 * ASTR;
        const float* B = Bs + (t & 1) * 32 * BSTR_P;
        #pragma unroll
        for (int kk = 0; kk < 32; kk += 8) {
            uint32_t af[4][4], bf[4][2];
            #pragma unroll
            for (int mt = 0; mt < 4; mt++) {
                int r = wm * 64 + mt * 16 + g;
                af[mt][0] = __float_as_uint(A[r * ASTR + kk + tg]);
                af[mt][1] = __float_as_uint(A[(r + 8) * ASTR + kk + tg]);
                af[mt][2] = __float_as_uint(A[r * ASTR + kk + tg + 4]);
                af[mt][3] = __float_as_uint(A[(r + 8) * ASTR + kk + tg + 4]);
            }
            #pragma unroll
            for (int nt = 0; nt < 4; nt++) {
                int nc = wn * 32 + nt * 8 + g;
                bf[nt][0] = __float_as_uint(B[(kk + tg) * BSTR_P + nc]);
                bf[nt][1] = __float_as_uint(B[(kk + tg + 4) * BSTR_P + nc]);
            }
            #pragma unroll
            for (int mt = 0; mt < 4; mt++)
                #pragma unroll
                for (int nt = 0; nt < 4; nt++)
                    mma_tf32(acc[mt][nt], af[mt], bf[nt]);
        }
        __syncthreads();   // done reading buffer t&1

        if (t < 6) {
            int k0 = (t + 2) * 32;
            uint32_t abase = AS_U + (uint32_t)(((t + 2) & 1) * 128 * ASTR * 4);
            uint32_t bbase = BS_U + (uint32_t)(((t + 2) & 1) * 32 * BSTR_P * 4);
            #pragma unroll
            for (int u = 0; u < 4; u++) {
                cp_async16z(abase + (uint32_t)(arow[u] * ASTR + akq[u]) * 4,
                            &wbase[u][k0 + akq[u]], wsz[u]);
                cp_async16(bbase + (uint32_t)(brow[u] * BSTR_P + bnq[u]) * 4,
                           &X[(size_t)(k0 + brow[u]) * NPIX + n0 + bnq[u]]);
            }
            cp_async_commit();
        }
    }

    // epilogue: q,k rows (<64) -> smem QKs; v rows -> g_Vb bf16
    float* QKs = sm;   // reuse (64 x 132 floats = 33792 < 71680)
    #pragma unroll
    for (int mt = 0; mt < 4; mt++) {
        int rbase = m0 + wm * 64 + mt * 16 + g;
        #pragma unroll
        for (int half = 0; half < 2; half++) {
            int r = rbase + half * 8;
            if (r >= OC_ALL) continue;
            float bias = (r < 32) ? bq[r] : (r < 64) ? bk[r - 32] : bv[r - 64];
            #pragma unroll
            for (int nt = 0; nt < 4; nt++) {
                int cl = wn * 32 + nt * 8 + 2 * tg;
                float v0 = acc[mt][nt][half * 2 + 0] + bias;
                float v1 = acc[mt][nt][half * 2 + 1] + bias;
                if (r < 64) {
                    QKs[r * QK_LD + cl]     = v0;
                    QKs[r * QK_LD + cl + 1] = v1;
                } else {
                    *(__nv_bfloat162*)&g_Vb[((size_t)b * CCH + (r - 64)) * NPIX + n0 + cl] =
                        __floats2bfloat162_rn(v0, v1);
                }
            }
        }
    }
    if (m0 != 0) return;
    __syncthreads();

    // augment (m-tile 0 only): 128 threads, one pixel each
    if (tid < 128) {
        int n = n0 + tid;
        float a0 = 0.f, a1 = 0.f;
        float q[DHEAD];
        #pragma unroll
        for (int d = 0; d < DHEAD; d++) {
            q[d] = QKs[d * QK_LD + tid];
            a0 += q[d] * Wr[2 * d];
            a1 += q[d] * Wr[2 * d + 1];
        }
        const float scale = rsqrtf((float)DHEAD);
        float* qrow = g_qa + (size_t)(b * NPIX + n) * ASTR2;
        #pragma unroll
        for (int d = 0; d < DHEAD; d++) qrow[d] = f2tf32(q[d] * scale);
        qrow[32] = f2tf32(a0 * scale);
        qrow[33] = f2tf32(a1 * scale);
        #pragma unroll
        for (int d = 34; d < KA; d++) qrow[d] = 0.f;

        float* krow = g_ka + (size_t)(b * NPIX + n) * ASTR2;
        #pragma unroll
        for (int d = 0; d < DHEAD; d++) krow[d] = f2tf32(QKs[(32 + d) * QK_LD + tid]);
        int hi = n >> 5, wi = n & 31;
        krow[32] = f2tf32(-(float)hi * (1.f / 31.f));
        krow[33] = f2tf32(-(float)wi * (1.f / 31.f));
        #pragma unroll
        for (int d = 34; d < KA; d++) krow[d] = 0.f;
    }
}

// ---------------------------------------------------------------------------
// 2) Fused attention: cp.async double-buffered Ks and Vs staging — unchanged
// ---------------------------------------------------------------------------
#define IB 64
#define JT 128
#define PSTRH 136
#define KSZ (128 * ASTR2 * 4)                   // 22528 B per Ks buffer
#define VSZ (CCH * PSTRH * 2)                   // 69632 B per Vs buffer
// byte offsets in dynamic smem
#define QS_B 0
#define KS_B (QS_B + IB * ASTR2 * 4)            // 11264
#define PS_B (KS_B + 2 * KSZ)                   // 56320
#define VS_B (PS_B + IB * PSTRH * 2)            // 73728
#define RS_B (VS_B + 2 * VSZ)                   // 212992
#define RI_B (RS_B + IB * 4)
#define FUSED_SMEM (RI_B + IB * 4)              // 213504

__global__ __launch_bounds__(512) void fused_attn(const float* __restrict__ x,
                                                  const float* __restrict__ gamma,
                                                  float* __restrict__ out) {
    int b  = blockIdx.y;
    int i0 = blockIdx.x * IB;
    const float* qab = g_qa + (size_t)b * NPIX * ASTR2;
    const float* kab = g_ka + (size_t)b * NPIX * ASTR2;
    const __nv_bfloat16* Vg = g_Vb + (size_t)b * CCH * NPIX;

    extern __shared__ char smc[];
    float* Qs = (float*)(smc + QS_B);
    __nv_bfloat16* PsH = (__nv_bfloat16*)(smc + PS_B);
    float* rs = (float*)(smc + RS_B);
    float* ri = (float*)(smc + RI_B);
    uint32_t smem_u = (uint32_t)__cvta_generic_to_shared(smc);

    int tid = threadIdx.x, warp = tid >> 5, lane = tid & 31;
    int wq = warp >> 3, wr = warp & 7;          // 2 (i) x 8 (j/ch) warp grid
    int g = lane >> 2, tg = lane & 3;

    // ldmatrix lane addresses (byte, shared space)
    uint32_t psA[2], vsB[2];
    {
        int sub = lane & 7;
        int ar = wq * 32 + ((lane >> 3) & 1) * 8 + sub;   // A: row
        int ac = (lane >> 4) * 8;                         // A: col (k)
        psA[0] = smem_u + PS_B + (uint32_t)(ar * PSTRH + ac) * 2;
        psA[1] = psA[0] + 16 * PSTRH * 2;
        int br = wr * 32 + (lane >> 4) * 8 + sub;         // B: row (channel)
        int bc = ((lane >> 3) & 1) * 8;                   // B: col (k)
        vsB[0] = smem_u + VS_B + (uint32_t)(br * PSTRH + bc) * 2;
        vsB[1] = vsB[0] + 16 * PSTRH * 2;
    }

    if (tid < IB) rs[tid] = 0.f;

    // staging index precompute
    int krow_[3], kc4_[3];                      // Ks: 1280 float4 chunks
    #pragma unroll
    for (int u = 0; u < 3; u++) {
        int idx = tid + u * 512;
        krow_[u] = idx / 10; kc4_[u] = (idx % 10) * 4;
    }
    int vrow_[8], vq8_[8];                      // Vs: 4096 16B chunks
    #pragma unroll
    for (int u = 0; u < 8; u++) {
        int idx = tid + u * 512;
        vrow_[u] = idx >> 4; vq8_[u] = (idx & 15) * 8;
    }

    // prologue: stage Qs (regular), cp.async Ks(0) + V(0)
    for (int idx = tid; idx < 640; idx += 512) {
        int row = idx / 10, c4 = (idx % 10) * 4;
        *(float4*)&Qs[row * ASTR2 + c4] = *(const float4*)&qab[(size_t)(i0 + row) * ASTR2 + c4];
    }
    #pragma unroll
    for (int u = 0; u < 3; u++) {
        if (u < 2 || tid < 256) {
            uint32_t dst = smem_u + KS_B + (uint32_t)(krow_[u] * ASTR2 + kc4_[u]) * 4;
            cp_async16(dst, &kab[(size_t)krow_[u] * ASTR2 + kc4_[u]]);
        }
    }
    #pragma unroll
    for (int u = 0; u < 8; u++) {
        uint32_t dst = smem_u + VS_B + (uint32_t)(vrow_[u] * PSTRH + vq8_[u]) * 2;
        cp_async16(dst, &Vg[(size_t)vrow_[u] * NPIX + vq8_[u]]);
    }
    cp_async_commit();
    cp_async_wait0();
    __syncthreads();

    float accO[2][4][4];
    #pragma unroll
    for (int mt = 0; mt < 2; mt++)
        #pragma unroll
        for (int nt = 0; nt < 4; nt++)
            #pragma unroll
            for (int r = 0; r < 4; r++) accO[mt][nt][r] = 0.f;
    float s[2][2] = {{0.f, 0.f}, {0.f, 0.f}};

    #pragma unroll 1
    for (int jt = 0; jt < 8; jt++) {
        // issue next-tile copies first; they drain across logits+exp+AV
        if (jt < 7) {
            int j1 = (jt + 1) * JT;
            uint32_t kbase = smem_u + KS_B + (uint32_t)(((jt + 1) & 1) * KSZ);
            #pragma unroll
            for (int u = 0; u < 3; u++) {
                if (u < 2 || tid < 256) {
                    uint32_t dst = kbase + (uint32_t)(krow_[u] * ASTR2 + kc4_[u]) * 4;
                    cp_async16(dst, &kab[(size_t)(j1 + krow_[u]) * ASTR2 + kc4_[u]]);
                }
            }
            uint32_t vbase = smem_u + VS_B + (uint32_t)(((jt + 1) & 1) * VSZ);
            #pragma unroll
            for (int u = 0; u < 8; u++) {
                uint32_t dst = vbase + (uint32_t)(vrow_[u] * PSTRH + vq8_[u]) * 2;
                cp_async16(dst, &Vg[(size_t)vrow_[u] * NPIX + j1 + vq8_[u]]);
            }
            cp_async_commit();
        }

        // logits: 64 x 128, K=40 (tf32). Warp: m32 (2 x m16) x n16 (2 x n8)
        const float* Kcur = (const float*)(smc + KS_B + (jt & 1) * KSZ);
        float accS[2][2][4];
        #pragma unroll
        for (int mt = 0; mt < 2; mt++)
            #pragma unroll
            for (int nt = 0; nt < 2; nt++)
                #pragma unroll
                for (int r = 0; r < 4; r++) accS[mt][nt][r] = 0.f;
        #pragma unroll
        for (int k = 0; k < 5; k++) {
            int kk = k * 8;
            uint32_t af[2][4];
            #pragma unroll
            for (int mt = 0; mt < 2; mt++) {
                int abase = (wq * 32 + mt * 16 + g) * ASTR2 + kk + tg;
                af[mt][0] = __float_as_uint(Qs[abase]);
                af[mt][1] = __float_as_uint(Qs[abase + 8 * ASTR2]);
                af[mt][2] = __float_as_uint(Qs[abase + 4]);
                af[mt][3] = __float_as_uint(Qs[abase + 8 * ASTR2 + 4]);
            }
            #pragma unroll
            for (int nt = 0; nt < 2; nt++) {
                uint32_t bf[2];
                int bb = (wr * 16 + nt * 8 + g) * ASTR2 + kk + tg;
                bf[0] = __float_as_uint(Kcur[bb]);
                bf[1] = __float_as_uint(Kcur[bb + 4]);
                #pragma unroll
                for (int mt = 0; mt < 2; mt++)
                    mma_tf32(accS[mt][nt], af[mt], bf);
            }
        }

        // exp + rowsum + write Ps (bf16 pairs)
        #pragma unroll
        for (int mt = 0; mt < 2; mt++) {
            int r0l = wq * 32 + mt * 16 + g;
            #pragma unroll
            for (int nt = 0; nt < 2; nt++) {
                float e0 = __expf(accS[mt][nt][0]);
                float e1 = __expf(accS[mt][nt][1]);
                float e2 = __expf(accS[mt][nt][2]);
                float e3 = __expf(accS[mt][nt][3]);
                s[mt][0] += e0 + e1; s[mt][1] += e2 + e3;
                int c = wr * 16 + nt * 8 + 2 * tg;
                *(__nv_bfloat162*)&PsH[r0l * PSTRH + c]       = __floats2bfloat162_rn(e0, e1);
                *(__nv_bfloat162*)&PsH[(r0l + 8) * PSTRH + c] = __floats2bfloat162_rn(e2, e3);
            }
        }
        __syncthreads();   // Ps visible (Vs(jt) already complete since prev iter)

        // AV: 64 x 256 += Ps(64x128) @ Vs(256x128)^T, bf16 k16, ldmatrix frags
        uint32_t voff = (uint32_t)((jt & 1) * VSZ);
        #pragma unroll
        for (int kk = 0; kk < 128; kk += 16) {
            uint32_t af[2][4];
            ldmatrix_x4(af[0][0], af[0][1], af[0][2], af[0][3], psA[0] + kk * 2);
            ldmatrix_x4(af[1][0], af[1][1], af[1][2], af[1][3], psA[1] + kk * 2);
            #pragma unroll
            for (int nt2 = 0; nt2 < 2; nt2++) {
                uint32_t b0, b1, b2, b3;
                ldmatrix_x4(b0, b1, b2, b3, vsB[nt2] + voff + kk * 2);
                uint32_t bfe[2] = {b0, b1};
                uint32_t bfo[2] = {b2, b3};
                #pragma unroll
                for (int mt = 0; mt < 2; mt++) {
                    mma_bf16(accO[mt][nt2 * 2 + 0], af[mt], bfe);
                    mma_bf16(accO[mt][nt2 * 2 + 1], af[mt], bfo);
                }
            }
        }

        cp_async_wait0();  // Ks(jt+1)+Vs(jt+1) arrived
        __syncthreads();   // all AV reads of Ps/Vs done before next exp/copies
    }

    // finalize row sums: reduce tg lanes, accumulate across wr warps
    #pragma unroll
    for (int mt = 0; mt < 2; mt++)
        #pragma unroll
        for (int h = 0; h < 2; h++) {
            float v = s[mt][h];
            v += __shfl_xor_sync(0xffffffffu, v, 1);
            v += __shfl_xor_sync(0xffffffffu, v, 2);
            if (tg == 0) atomicAdd(&rs[wq * 32 + mt * 16 + h * 8 + g], v);
        }
    __syncthreads();
    if (tid < IB) ri[tid] = gamma[0] / rs[tid];
    __syncthreads();

    // epilogue: out[b,c,i] = ri[i] * acc + x[b,c,i]
    #pragma unroll
    for (int mt = 0; mt < 2; mt++) {
        int r0l = wq * 32 + mt * 16 + g;
        float inv0 = ri[r0l], inv1 = ri[r0l + 8];
        #pragma unroll
        for (int nt = 0; nt < 4; nt++) {
            int ch = wr * 32 + nt * 8 + 2 * tg;
            size_t b0 = ((size_t)b * CCH + ch) * NPIX + i0 + r0l;
            size_t b1 = b0 + NPIX;                 // ch+1
            out[b0]     = accO[mt][nt][0] * inv0 + x[b0];
            out[b1]     = accO[mt][nt][1] * inv0 + x[b1];
            out[b0 + 8] = accO[mt][nt][2] * inv1 + x[b0 + 8];
            out[b1 + 8] = accO[mt][nt][3] * inv1 + x[b1 + 8];
        }
    }
}

// ---------------------------------------------------------------------------
extern "C" void kernel_launch(void* const* d_in, const int* in_sizes, int n_in,
                              void* d_out, int out_size) {
    const float* x     = (const float*)d_in[0];
    const float* Wq    = (const float*)d_in[1];
    const float* bq    = (const float*)d_in[2];
    const float* Wk    = (const float*)d_in[3];
    const float* bk    = (const float*)d_in[4];
    const float* Wv    = (const float*)d_in[5];
    const float* bv    = (const float*)d_in[6];
    const float* Wr    = (const float*)d_in[7];
    const float* gamma = (const float*)d_in[9];
    float* out = (float*)d_out;

    cudaFuncSetAttribute(proj_gemm_mma, cudaFuncAttributeMaxDynamicSharedMemorySize, PROJ_SMEM);
    cudaFuncSetAttribute(fused_attn, cudaFuncAttributeMaxDynamicSharedMemorySize, FUSED_SMEM);

    proj_gemm_mma<<<dim3(NPIX / 128, 3, BATCH), 256, PROJ_SMEM>>>(x, Wq, bq, Wk, bk, Wv, bv, Wr);
    fused_attn<<<dim3(NPIX / IB, BATCH), 512, FUSED_SMEM>>>(x, gamma, out);
}